// round 15
// baseline (speedup 1.0000x reference)
#include <cuda_runtime.h>
#include <cuda_bf16.h>
#include <cuda_fp16.h>
#include <cstdint>

#define BB 16
#define HH 48
#define WWD 48
#define CC 128
#define NHH 8
#define SSW 8
#define LL (HH*WWD)
#define HD (CC/NHH)          // 16
#define NWIN (WWD/SSW)       // 6
#define SEQ (HH*SSW)         // 384

// scratch (no allocations allowed)
__device__ float g_pooled[BB*9*CC];

typedef unsigned long long ull;
typedef unsigned int u32;

// pack {lo=f16(x), hi=f16(y)}
__device__ __forceinline__ u32 cvt_h2(float x, float y){
  u32 d; asm("cvt.rn.f16x2.f32 %0,%1,%2;" : "=r"(d) : "f"(y), "f"(x)); return d;
}
__device__ __forceinline__ u32 ex2h2(u32 x){
  u32 d; asm("ex2.approx.f16x2 %0,%1;" : "=r"(d) : "r"(x)); return d;
}
// fp32-accumulate f16 MMA
__device__ __forceinline__ void mma_f16(float (&d)[4], const u32 (&a)[4], u32 b0, u32 b1){
  asm volatile("mma.sync.aligned.m16n8k16.row.col.f32.f16.f16.f32 "
    "{%0,%1,%2,%3}, {%4,%5,%6,%7}, {%8,%9}, {%0,%1,%2,%3};"
    : "+f"(d[0]), "+f"(d[1]), "+f"(d[2]), "+f"(d[3])
    : "r"(a[0]), "r"(a[1]), "r"(a[2]), "r"(a[3]), "r"(b0), "r"(b1));
}
// fp16-accumulate f16 MMA, separate zero C (no accumulator zeroing in loop)
__device__ __forceinline__ void mma_f16h(u32& d0, u32& d1, const u32 (&a)[4],
                                         u32 b0, u32 b1, u32 zc){
  asm volatile("mma.sync.aligned.m16n8k16.row.col.f16.f16.f16.f16 "
    "{%0,%1}, {%2,%3,%4,%5}, {%6,%7}, {%8,%9};"
    : "=r"(d0), "=r"(d1)
    : "r"(a[0]), "r"(a[1]), "r"(a[2]), "r"(a[3]), "r"(b0), "r"(b1),
      "r"(zc), "r"(zc));
}

// ---------------------------------------------------------------------------
// Kernel 1: adaptive avg pool to 3x3 (uniform 16x16 block means)
// grid (9 bins, 16 batches, 8 ch eighths), 256 threads, 4 float4 loads each
// ---------------------------------------------------------------------------
__global__ void pool_kernel(const float* __restrict__ v){
  const int bin = blockIdx.x, b = blockIdx.y, ch = blockIdx.z;
  const int ky = bin / 3, kx = bin - ky*3;
  const int tid = threadIdx.x;
  const int c4 = tid & 3, part = tid >> 2;     // 4 cg per block, 64 parts
  const int row = part >> 2, quad = part & 3;  // 16 rows x 4 col-quads
  const int cg = ch*4 + c4;
  const float4* vb = (const float4*)(v + (size_t)b*LL*CC);
  const int h = ky*16 + row;
  const float4* p = vb + (size_t)(h*WWD + kx*16 + quad*4)*(CC/4) + cg;
  float4 s = make_float4(0.f,0.f,0.f,0.f);
  #pragma unroll
  for (int ww = 0; ww < 4; ww++){
    float4 t = p[ww*(CC/4)];
    s.x += t.x; s.y += t.y; s.z += t.z; s.w += t.w;
  }
  __shared__ float4 red[256];
  red[tid] = s; __syncthreads();
  #pragma unroll
  for (int off = 128; off >= 4; off >>= 1){
    if (tid < off){
      float4 o = red[tid+off];
      s.x += o.x; s.y += o.y; s.z += o.z; s.w += o.w;
      red[tid] = s;
    }
    __syncthreads();
  }
  if (tid < 4){
    s.x *= (1.f/256.f); s.y *= (1.f/256.f); s.z *= (1.f/256.f); s.w *= (1.f/256.f);
    ((float4*)g_pooled)[(b*9 + bin)*32 + ch*4 + tid] = s;
  }
}

// ---------------------------------------------------------------------------
// Kernel 2: tensor-core attention with the proj MLP folded into the fill
// phase (proj kernel eliminated). MLP stages use the sK smem region for
// pooled/act staging BEFORE the K fill overwrites it (sync-fenced).
// Mainloop/epilogue identical to the R13 best (45.8us).
// grid (8 heads, 6 wblks, 16 batches), 256 threads, 3 CTAs/SM
// ---------------------------------------------------------------------------
#define KOFF    0
#define VOFF    12288
#define HOFF    24576       // halo fp16: 50*10*16*2 = 16000
#define W2_OFF  40576
#define B2_OFF  40864
#define SMEM_SZ 40896
#define ONES16  0x3C003C00u

__global__ void __launch_bounds__(256, 3)
attn_kernel(const float* __restrict__ q, const float* __restrict__ k,
            const float* __restrict__ v, float* __restrict__ out,
            const float* __restrict__ p1w, const float* __restrict__ p1b,
            const float* __restrict__ bng, const float* __restrict__ bnb,
            const float* __restrict__ bnm, const float* __restrict__ bnv,
            const float* __restrict__ p2w, const float* __restrict__ p2b,
            const float* __restrict__ dynw, const float* __restrict__ dynb){
  extern __shared__ char smem[];
  char* sK  = smem + KOFF;
  char* sV  = smem + VOFF;
  __half2* haloh = (__half2*)(smem + HOFF);   // [50*10][8] half2
  __half2* sW2 = (__half2*)(smem + W2_OFF);   // [9][8]
  __half2* sB2 = (__half2*)(smem + B2_OFF);   // [8]

  const int head = blockIdx.x, wblk = blockIdx.y, b = blockIdx.z;
  const int c0 = head*HD;
  const int wb0 = wblk*SSW;
  const int tid = threadIdx.x;
  const int wid = tid >> 5, lane = tid & 31;
  const int grp = lane >> 2, tig = lane & 3;
  const size_t bbase = (size_t)b*LL*CC;

  // ================= inline proj MLP (uses sK region as staging) ==========
  {
    float* ps  = (float*)sK;         // [10][128]: pos 0..8 pooled, 9 = mean
    float* act = ps + 1280;          // [10][32]
    for (int i = tid; i < 1152; i += 256) ps[i] = g_pooled[b*1152 + i];
    __syncthreads();
    if (tid < 128){
      float s = 0.f;
      #pragma unroll
      for (int p = 0; p < 9; p++) s += ps[p*128 + tid];
      ps[1152 + tid] = s * (1.f/9.f);
    }
    __syncthreads();
    // stage A: 10 pos x 32 outputs
    for (int t = tid; t < 320; t += 256){
      int pos = t >> 5, o = t & 31;
      float s = p1b[o];
      const float4* w = (const float4*)(p1w + o*CC);
      const float* prow = ps + pos*128;
      #pragma unroll 8
      for (int i = 0; i < 32; i++){
        float4 ww = w[i];
        s += ww.x*prow[4*i] + ww.y*prow[4*i+1] + ww.z*prow[4*i+2] + ww.w*prow[4*i+3];
      }
      float inv = rsqrtf(bnv[o] + 1e-5f);
      s = (s - bnm[o]) * (inv * bng[o]) + bnb[o];
      s = 0.5f * s * (1.f + erff(s * 0.70710678118654752f));
      act[t] = s;
    }
    __syncthreads();
    // stage B: 10 pos x 8 channel-pairs (this head's 16 channels only)
    if (tid < 80){
      int pos = tid / 8, pr = tid & 7;
      const float* ac = act + pos*32;
      float y0[4], y1[4];
      #pragma unroll
      for (int g = 0; g < 4; g++){
        int oc0 = g*CC + c0 + 2*pr;
        float s0 = p2b[oc0], s1 = p2b[oc0+1];
        const float4* w0 = (const float4*)(p2w + oc0*32);
        const float4* w1 = (const float4*)(p2w + (oc0+1)*32);
        #pragma unroll
        for (int i = 0; i < 8; i++){
          float4 a0 = w0[i], a1 = w1[i];
          float e0 = ac[4*i], e1 = ac[4*i+1], e2 = ac[4*i+2], e3 = ac[4*i+3];
          s0 += a0.x*e0 + a0.y*e1 + a0.z*e2 + a0.w*e3;
          s1 += a1.x*e0 + a1.y*e1 + a1.z*e2 + a1.w*e3;
        }
        y0[g] = s0; y1[g] = s1;
      }
      float m0 = fmaxf(fmaxf(y0[0],y0[1]), fmaxf(y0[2],y0[3]));
      float m1 = fmaxf(fmaxf(y1[0],y1[1]), fmaxf(y1[2],y1[3]));
      float e00 = expf(y0[0]-m0), e01 = expf(y0[1]-m0), e02 = expf(y0[2]-m0), e03 = expf(y0[3]-m0);
      float e10 = expf(y1[0]-m1), e11 = expf(y1[1]-m1), e12 = expf(y1[2]-m1), e13 = expf(y1[3]-m1);
      float r0 = 1.f/(e00+e01+e02+e03), r1 = 1.f/(e10+e11+e12+e13);
      int ca = c0 + 2*pr, cb = ca + 1;
      if (pos < 9){
        float wv0 = (e00*dynw[(0*CC+ca)*9+pos] + e01*dynw[(1*CC+ca)*9+pos]
                   + e02*dynw[(2*CC+ca)*9+pos] + e03*dynw[(3*CC+ca)*9+pos]) * r0;
        float wv1 = (e10*dynw[(0*CC+cb)*9+pos] + e11*dynw[(1*CC+cb)*9+pos]
                   + e12*dynw[(2*CC+cb)*9+pos] + e13*dynw[(3*CC+cb)*9+pos]) * r1;
        sW2[pos*8 + pr] = __floats2half2_rn(wv0, wv1);
      } else {
        float bv0 = (e00*dynb[0*CC+ca] + e01*dynb[1*CC+ca]
                   + e02*dynb[2*CC+ca] + e03*dynb[3*CC+ca]) * r0;
        float bv1 = (e10*dynb[0*CC+cb] + e11*dynb[1*CC+cb]
                   + e12*dynb[2*CC+cb] + e13*dynb[3*CC+cb]) * r1;
        sB2[pr] = __floats2half2_rn(bv0, bv1);
      }
    }
    __syncthreads();   // staging done; sK free for K fill; sW2/sB2 final
  }

  // ---- fill K (fp16, frag-packed: lane 16B = kh0|kh1) ----
  for (int i = tid; i < SEQ*4; i += 256){
    int key = i >> 2, dq = (i & 3)*4;
    int hj = key >> 3, wj = key & 7;
    float4 kv = *(const float4*)(k + bbase + (size_t)(hj*WWD + wb0 + wj)*CC + c0 + dq);
    u32 h0 = cvt_h2(kv.x, kv.y);
    u32 h1 = cvt_h2(kv.z, kv.w);
    int j0 = dq >> 1;                         // pair index 0,2,4,6
    int s0 = (j0 < 4) ? 2*j0 : 2*j0 - 7;
    int s1 = (j0+1 < 4) ? 2*(j0+1) : 2*(j0+1) - 7;
    int p0 = s0*4, p1 = s1*4;
    int step = key >> 4, r = key & 15;
    char* base = sK + step*512 + (r & 7)*64 + ((r >= 8) ? 8 : 0);
    *(u32*)(base + (p0 >> 3)*16 + (p0 & 7)) = h0;
    *(u32*)(base + (p1 >> 3)*16 + (p1 & 7)) = h1;
  }
  // ---- fill V (fp16 transposed, frag-packed) + interior halo from same load ----
  for (int i = tid; i < SEQ*4; i += 256){
    int key = i >> 2, dq = (i & 3)*4;
    int hj = key >> 3, wj = key & 7;
    float4 vv = *(const float4*)(v + bbase + (size_t)(hj*WWD + wb0 + wj)*CC + c0 + dq);
    float vals[4] = {vv.x, vv.y, vv.z, vv.w};
    int blk = key >> 4, r = key & 15;
    int pr = r >> 1;
    int slot = (r < 8) ? 2*pr : 2*(pr-4)+1;
    int q0 = slot*4 + (r & 1)*2;
    char* base = sV + blk*512 + (q0 >> 3)*16 + (q0 & 7);
    #pragma unroll
    for (int d = 0; d < 4; d++){
      int ch = dq + d;
      *(__half*)(base + (ch & 7)*64 + ((ch >= 8) ? 8 : 0)) = __float2half(vals[d]);
    }
    // interior halo position (hj+1, wj+1): same data, fp16 packed pairs
    int hpos = (hj + 1)*10 + (wj + 1);
    haloh[hpos*8 + (dq >> 1)]     = __floats2half2_rn(vals[0], vals[1]);
    haloh[hpos*8 + (dq >> 1) + 1] = __floats2half2_rn(vals[2], vals[3]);
  }
  // ---- boundary halo (116 positions x 4 ch-quads), bounds-checked ----
  for (int i = tid; i < 464; i += 256){
    int dq = i & 3, idx = i >> 2;        // idx in [0,116)
    int hh, ww;
    if (idx < 10){ hh = 0;  ww = idx; }
    else if (idx < 20){ hh = 49; ww = idx - 10; }
    else { int j = idx - 20; hh = 1 + (j >> 1); ww = (j & 1)*9; }
    int gh = hh - 1, gw = wb0 + ww - 1;
    float4 val = make_float4(0.f,0.f,0.f,0.f);
    if (gh >= 0 && gh < HH && gw >= 0 && gw < WWD)
      val = *(const float4*)(v + bbase + (size_t)(gh*WWD + gw)*CC + c0 + dq*4);
    haloh[(hh*10 + ww)*8 + dq*2]     = __floats2half2_rn(val.x, val.y);
    haloh[(hh*10 + ww)*8 + dq*2 + 1] = __floats2half2_rn(val.z, val.w);
  }

  // ---- Q fragments (scaled fp16) ----
  const float SCL = 0.36067376022224085f;  // 0.25 * log2(e)
  u32 aq[3][4];
  #pragma unroll
  for (int mf = 0; mf < 3; mf++){
    #pragma unroll
    for (int rs = 0; rs < 2; rs++){
      int m = wid*48 + mf*16 + grp + rs*8;     // query 0..383
      int hl = m >> 3, w = m & 7;
      const float* qr = q + bbase + (size_t)(hl*WWD + wb0 + w)*CC + c0;
      float2 qa = *(const float2*)(qr + 2*tig);
      float2 qb = *(const float2*)(qr + 2*tig + 8);
      aq[mf][rs]   = cvt_h2(qa.x*SCL, qa.y*SCL);
      aq[mf][rs+2] = cvt_h2(qb.x*SCL, qb.y*SCL);
    }
  }
  __syncthreads();

  float o[3][2][4];
  #pragma unroll
  for (int mf = 0; mf < 3; mf++)
    #pragma unroll
    for (int cn = 0; cn < 2; cn++)
      #pragma unroll
      for (int r = 0; r < 4; r++) o[mf][cn][r] = 0.f;
  float lsd[3][4];
  #pragma unroll
  for (int mf = 0; mf < 3; mf++)
    #pragma unroll
    for (int r = 0; r < 4; r++) lsd[mf][r] = 0.f;

  const u32 zc = 0u;
  const int start = wid*3;   // warp-skewed ring start (linearized)

  #define STEP(T)                                                            \
  {                                                                          \
    const int lbase = (T)*512 + grp*64 + tig*16;                             \
    uint4 kk = *(const uint4*)(sK + lbase);                                  \
    uint4 vk = *(const uint4*)(sV + lbase);                                  \
    _Pragma("unroll")                                                        \
    for (int mf = 0; mf < 3; mf++){                                          \
      u32 d00, d01, d10, d11;                                                \
      mma_f16h(d00, d01, aq[mf], kk.x, kk.y, zc);                            \
      mma_f16h(d10, d11, aq[mf], kk.z, kk.w, zc);                            \
      u32 pa[4];                                                             \
      pa[0] = ex2h2(d00);                                                    \
      pa[1] = ex2h2(d01);                                                    \
      pa[2] = ex2h2(d10);                                                    \
      pa[3] = ex2h2(d11);                                                    \
      mma_f16(o[mf][0], pa, vk.x, vk.y);                                     \
      mma_f16(o[mf][1], pa, vk.z, vk.w);                                     \
      mma_f16(lsd[mf], pa, ONES16, ONES16);                                  \
    }                                                                        \
  }

  #pragma unroll 4
  for (int t = start; t < 24; t++) STEP(t)
  #pragma unroll 4
  for (int t = 0; t < start; t++) STEP(t)
  #undef STEP

  // ---- epilogue: HFMA2 conv + bias + normalize + store (R13 form) ----
  #pragma unroll
  for (int mf = 0; mf < 3; mf++){
    float rinv0 = 1.0f / lsd[mf][0];     // row grp (all D cols = row sum)
    float rinv1 = 1.0f / lsd[mf][2];     // row grp+8
    #pragma unroll
    for (int rs = 0; rs < 2; rs++){
      int m = wid*48 + mf*16 + grp + rs*8;
      int hl = m >> 3, w = m & 7;
      float rinv = rs ? rinv1 : rinv0;
      float* orow = out + bbase + (size_t)(hl*WWD + wb0 + w)*CC + c0;
      #pragma unroll
      for (int cn = 0; cn < 2; cn++){
        int cp = cn*4 + tig;     // channel pair index
        __half2 acc = sB2[cp];
        #pragma unroll
        for (int t = 0; t < 9; t++){
          int dy = t/3, dx = t - dy*3;
          acc = __hfma2(sW2[t*8+cp], haloh[((hl+dy)*10 + (w+dx))*8 + cp], acc);
        }
        float2 cv = __half22float2(acc);
        float2 res;
        res.x = o[mf][cn][rs*2]   * rinv + cv.x;
        res.y = o[mf][cn][rs*2+1] * rinv + cv.y;
        *(float2*)(orow + cn*8 + 2*tig) = res;
      }
    }
  }
}

// ---------------------------------------------------------------------------
extern "C" void kernel_launch(void* const* d_in, const int* in_sizes, int n_in,
                              void* d_out, int out_size){
  const float* q    = (const float*)d_in[0];
  const float* k    = (const float*)d_in[1];
  const float* v    = (const float*)d_in[2];
  const float* p1w  = (const float*)d_in[3];
  const float* p1b  = (const float*)d_in[4];
  const float* bng  = (const float*)d_in[5];
  const float* bnb  = (const float*)d_in[6];
  const float* bnm  = (const float*)d_in[7];
  const float* bnv  = (const float*)d_in[8];
  const float* p2w  = (const float*)d_in[9];
  const float* p2b  = (const float*)d_in[10];
  const float* dynw = (const float*)d_in[11];
  const float* dynb = (const float*)d_in[12];
  float* out = (float*)d_out;

  cudaFuncSetAttribute(attn_kernel, cudaFuncAttributeMaxDynamicSharedMemorySize, SMEM_SZ);

  pool_kernel<<<dim3(9, BB, 8), 256>>>(v);
  attn_kernel<<<dim3(NHH, NWIN, BB), 256, SMEM_SZ>>>(q, k, v, out,
      p1w, p1b, bng, bnb, bnm, bnv, p2w, p2b, dynw, dynb);
}

// round 16
// speedup vs baseline: 1.9382x; 1.9382x over previous
#include <cuda_runtime.h>
#include <cuda_bf16.h>
#include <cuda_fp16.h>
#include <cstdint>

#define BB 16
#define HH 48
#define WWD 48
#define CC 128
#define NHH 8
#define SSW 8
#define LL (HH*WWD)
#define HD (CC/NHH)          // 16
#define NWIN (WWD/SSW)       // 6
#define SEQ (HH*SSW)         // 384

// scratch (no allocations allowed)
__device__ float g_pooled[BB*9*CC];
__device__ float g_w[BB*CC*9];
__device__ float g_bias[BB*CC];

typedef unsigned long long ull;
typedef unsigned int u32;

// pack {lo=f16(x), hi=f16(y)}
__device__ __forceinline__ u32 cvt_h2(float x, float y){
  u32 d; asm("cvt.rn.f16x2.f32 %0,%1,%2;" : "=r"(d) : "f"(y), "f"(x)); return d;
}
__device__ __forceinline__ u32 ex2h2(u32 x){
  u32 d; asm("ex2.approx.f16x2 %0,%1;" : "=r"(d) : "r"(x)); return d;
}
// fp32-accumulate f16 MMA
__device__ __forceinline__ void mma_f16(float (&d)[4], const u32 (&a)[4], u32 b0, u32 b1){
  asm volatile("mma.sync.aligned.m16n8k16.row.col.f32.f16.f16.f32 "
    "{%0,%1,%2,%3}, {%4,%5,%6,%7}, {%8,%9}, {%0,%1,%2,%3};"
    : "+f"(d[0]), "+f"(d[1]), "+f"(d[2]), "+f"(d[3])
    : "r"(a[0]), "r"(a[1]), "r"(a[2]), "r"(a[3]), "r"(b0), "r"(b1));
}
// fp16-accumulate f16 MMA, separate zero C (no accumulator zeroing in loop)
__device__ __forceinline__ void mma_f16h(u32& d0, u32& d1, const u32 (&a)[4],
                                         u32 b0, u32 b1, u32 zc){
  asm volatile("mma.sync.aligned.m16n8k16.row.col.f16.f16.f16.f16 "
    "{%0,%1}, {%2,%3,%4,%5}, {%6,%7}, {%8,%9};"
    : "=r"(d0), "=r"(d1)
    : "r"(a[0]), "r"(a[1]), "r"(a[2]), "r"(a[3]), "r"(b0), "r"(b1),
      "r"(zc), "r"(zc));
}

// ---------------------------------------------------------------------------
// Kernel 1: adaptive avg pool to 3x3 — warp-per-position coalescing.
// A warp reads one spatial position's FULL 512B channel row (32 lanes x
// float4, perfectly coalesced). 8 warps sweep the 256 positions of the
// 16x16 pool block in 32 iterations (2 ILP accumulators), then a 3-level
// cross-warp tree. grid (9 bins, 16 batches), 256 threads.
// ---------------------------------------------------------------------------
__global__ void pool_kernel(const float* __restrict__ v){
  const int bin = blockIdx.x, b = blockIdx.y;
  const int ky = bin / 3, kx = bin - ky*3;
  const int tid = threadIdx.x;
  const int wp = tid >> 5, lane = tid & 31;
  const float4* vb = (const float4*)(v + (size_t)b*LL*CC);
  float4 a0 = make_float4(0.f,0.f,0.f,0.f), a1 = a0;
  #pragma unroll
  for (int i = 0; i < 32; i += 2){
    int p0 = wp + (i+0)*8;       // position within 16x16 block
    int p1 = wp + (i+1)*8;
    int r0 = p0 >> 4, c0 = p0 & 15;
    int r1 = p1 >> 4, c1 = p1 & 15;
    float4 t0 = vb[((size_t)((ky*16 + r0)*WWD + kx*16 + c0))*(CC/4) + lane];
    float4 t1 = vb[((size_t)((ky*16 + r1)*WWD + kx*16 + c1))*(CC/4) + lane];
    a0.x += t0.x; a0.y += t0.y; a0.z += t0.z; a0.w += t0.w;
    a1.x += t1.x; a1.y += t1.y; a1.z += t1.z; a1.w += t1.w;
  }
  a0.x += a1.x; a0.y += a1.y; a0.z += a1.z; a0.w += a1.w;
  __shared__ float4 red[8][32];
  red[wp][lane] = a0; __syncthreads();
  if (tid < 128){
    float4 o = red[wp+4][lane];
    a0 = red[wp][lane];
    a0.x += o.x; a0.y += o.y; a0.z += o.z; a0.w += o.w;
    red[wp][lane] = a0;
  }
  __syncthreads();
  if (tid < 64){
    float4 o = red[wp+2][lane];
    a0 = red[wp][lane];
    a0.x += o.x; a0.y += o.y; a0.z += o.z; a0.w += o.w;
    red[wp][lane] = a0;
  }
  __syncthreads();
  if (tid < 32){
    float4 o = red[1][lane];
    a0 = red[0][lane];
    a0.x = (a0.x + o.x)*(1.f/256.f);
    a0.y = (a0.y + o.y)*(1.f/256.f);
    a0.z = (a0.z + o.z)*(1.f/256.f);
    a0.w = (a0.w + o.w)*(1.f/256.f);
    ((float4*)g_pooled)[(b*9 + bin)*32 + lane] = a0;
  }
}

// ---------------------------------------------------------------------------
// Kernel 2: proj MLP, one (batch, position) per block; pos 9 = global mean
// ---------------------------------------------------------------------------
__global__ void proj_kernel(const float* __restrict__ p1w, const float* __restrict__ p1b,
                            const float* __restrict__ bng, const float* __restrict__ bnb,
                            const float* __restrict__ bnm, const float* __restrict__ bnv,
                            const float* __restrict__ p2w, const float* __restrict__ p2b,
                            const float* __restrict__ dynw, const float* __restrict__ dynb){
  const int b = blockIdx.x, pos = blockIdx.y;
  const int tid = threadIdx.x;
  __shared__ float prow[128];
  __shared__ float act[32];

  {
    float s;
    if (pos < 9) s = g_pooled[(b*9 + pos)*CC + tid];
    else {
      s = 0.f;
      #pragma unroll
      for (int qq = 0; qq < 9; qq++) s += g_pooled[(b*9 + qq)*CC + tid];
      s *= (1.f/9.f);
    }
    prow[tid] = s;
  }
  __syncthreads();

  if (tid < 32){
    const int o = tid;
    float s = p1b[o];
    const float4* w = (const float4*)(p1w + o*CC);
    #pragma unroll 8
    for (int i = 0; i < 32; i++){
      float4 ww = w[i];
      s += ww.x*prow[4*i] + ww.y*prow[4*i+1] + ww.z*prow[4*i+2] + ww.w*prow[4*i+3];
    }
    float inv = rsqrtf(bnv[o] + 1e-5f);
    s = (s - bnm[o]) * (inv * bng[o]) + bnb[o];
    s = 0.5f * s * (1.f + erff(s * 0.70710678118654752f));
    act[o] = s;
  }
  __syncthreads();

  {
    const int c = tid;
    float y[4];
    #pragma unroll
    for (int g = 0; g < 4; g++){
      int oc = g*CC + c;
      float s = p2b[oc];
      const float4* w = (const float4*)(p2w + oc*32);
      #pragma unroll
      for (int i = 0; i < 8; i++){
        float4 ww = w[i];
        s += ww.x*act[4*i] + ww.y*act[4*i+1] + ww.z*act[4*i+2] + ww.w*act[4*i+3];
      }
      y[g] = s;
    }
    float m = fmaxf(fmaxf(y[0],y[1]), fmaxf(y[2],y[3]));
    float e0 = expf(y[0]-m), e1 = expf(y[1]-m), e2 = expf(y[2]-m), e3 = expf(y[3]-m);
    float rs = 1.f / (e0+e1+e2+e3);
    if (pos < 9){
      float wv = e0*dynw[(0*CC+c)*9+pos] + e1*dynw[(1*CC+c)*9+pos]
               + e2*dynw[(2*CC+c)*9+pos] + e3*dynw[(3*CC+c)*9+pos];
      g_w[(b*CC + c)*9 + pos] = wv * rs;
    } else {
      float bv = e0*dynb[0*CC+c] + e1*dynb[1*CC+c] + e2*dynb[2*CC+c] + e3*dynb[3*CC+c];
      g_bias[b*CC + c] = bv * rs;
    }
  }
}

// ---------------------------------------------------------------------------
// Kernel 3: tensor-core attention — EXACT R13 best (45.8us) configuration.
// grid (8 heads, 6 wblks, 16 batches), 256 threads, 3 CTAs/SM
// ---------------------------------------------------------------------------
#define KOFF    0
#define VOFF    12288
#define HOFF    24576       // halo fp16: 50*10*16*2 = 16000
#define W2_OFF  40576
#define B2_OFF  40864
#define SMEM_SZ 40896
#define ONES16  0x3C003C00u

__global__ void __launch_bounds__(256, 3)
attn_kernel(const float* __restrict__ q, const float* __restrict__ k,
            const float* __restrict__ v, float* __restrict__ out){
  extern __shared__ char smem[];
  char* sK  = smem + KOFF;
  char* sV  = smem + VOFF;
  __half2* haloh = (__half2*)(smem + HOFF);   // [50*10][8] half2
  __half2* sW2 = (__half2*)(smem + W2_OFF);   // [9][8]
  __half2* sB2 = (__half2*)(smem + B2_OFF);   // [8]

  const int head = blockIdx.x, wblk = blockIdx.y, b = blockIdx.z;
  const int c0 = head*HD;
  const int wb0 = wblk*SSW;
  const int tid = threadIdx.x;
  const int wid = tid >> 5, lane = tid & 31;
  const int grp = lane >> 2, tig = lane & 3;
  const size_t bbase = (size_t)b*LL*CC;

  // ---- fill K (fp16, frag-packed: lane 16B = kh0|kh1) ----
  for (int i = tid; i < SEQ*4; i += 256){
    int key = i >> 2, dq = (i & 3)*4;
    int hj = key >> 3, wj = key & 7;
    float4 kv = *(const float4*)(k + bbase + (size_t)(hj*WWD + wb0 + wj)*CC + c0 + dq);
    u32 h0 = cvt_h2(kv.x, kv.y);
    u32 h1 = cvt_h2(kv.z, kv.w);
    int j0 = dq >> 1;                         // pair index 0,2,4,6
    int s0 = (j0 < 4) ? 2*j0 : 2*j0 - 7;
    int s1 = (j0+1 < 4) ? 2*(j0+1) : 2*(j0+1) - 7;
    int p0 = s0*4, p1 = s1*4;
    int step = key >> 4, r = key & 15;
    char* base = sK + step*512 + (r & 7)*64 + ((r >= 8) ? 8 : 0);
    *(u32*)(base + (p0 >> 3)*16 + (p0 & 7)) = h0;
    *(u32*)(base + (p1 >> 3)*16 + (p1 & 7)) = h1;
  }
  // ---- fill V (fp16 transposed, frag-packed) + interior halo from same load ----
  for (int i = tid; i < SEQ*4; i += 256){
    int key = i >> 2, dq = (i & 3)*4;
    int hj = key >> 3, wj = key & 7;
    float4 vv = *(const float4*)(v + bbase + (size_t)(hj*WWD + wb0 + wj)*CC + c0 + dq);
    float vals[4] = {vv.x, vv.y, vv.z, vv.w};
    int blk = key >> 4, r = key & 15;
    int pr = r >> 1;
    int slot = (r < 8) ? 2*pr : 2*(pr-4)+1;
    int q0 = slot*4 + (r & 1)*2;
    char* base = sV + blk*512 + (q0 >> 3)*16 + (q0 & 7);
    #pragma unroll
    for (int d = 0; d < 4; d++){
      int ch = dq + d;
      *(__half*)(base + (ch & 7)*64 + ((ch >= 8) ? 8 : 0)) = __float2half(vals[d]);
    }
    // interior halo position (hj+1, wj+1): same data, fp16 packed pairs
    int hpos = (hj + 1)*10 + (wj + 1);
    haloh[hpos*8 + (dq >> 1)]     = __floats2half2_rn(vals[0], vals[1]);
    haloh[hpos*8 + (dq >> 1) + 1] = __floats2half2_rn(vals[2], vals[3]);
  }
  // ---- boundary halo (116 positions x 4 ch-quads), bounds-checked ----
  for (int i = tid; i < 464; i += 256){
    int dq = i & 3, idx = i >> 2;        // idx in [0,116)
    int hh, ww;
    if (idx < 10){ hh = 0;  ww = idx; }
    else if (idx < 20){ hh = 49; ww = idx - 10; }
    else { int j = idx - 20; hh = 1 + (j >> 1); ww = (j & 1)*9; }
    int gh = hh - 1, gw = wb0 + ww - 1;
    float4 val = make_float4(0.f,0.f,0.f,0.f);
    if (gh >= 0 && gh < HH && gw >= 0 && gw < WWD)
      val = *(const float4*)(v + bbase + (size_t)(gh*WWD + gw)*CC + c0 + dq*4);
    haloh[(hh*10 + ww)*8 + dq*2]     = __floats2half2_rn(val.x, val.y);
    haloh[(hh*10 + ww)*8 + dq*2 + 1] = __floats2half2_rn(val.z, val.w);
  }
  if (tid < 72){
    int t = tid >> 3, i = tid & 7;
    sW2[t*8+i] = __floats2half2_rn(g_w[(b*CC + c0 + 2*i)*9 + t],
                                   g_w[(b*CC + c0 + 2*i+1)*9 + t]);
  }
  if (tid < 8)
    sB2[tid] = __floats2half2_rn(g_bias[b*CC + c0 + 2*tid],
                                 g_bias[b*CC + c0 + 2*tid+1]);

  // ---- Q fragments (scaled fp16) ----
  const float SCL = 0.36067376022224085f;  // 0.25 * log2(e)
  u32 aq[3][4];
  #pragma unroll
  for (int mf = 0; mf < 3; mf++){
    #pragma unroll
    for (int rs = 0; rs < 2; rs++){
      int m = wid*48 + mf*16 + grp + rs*8;     // query 0..383
      int hl = m >> 3, w = m & 7;
      const float* qr = q + bbase + (size_t)(hl*WWD + wb0 + w)*CC + c0;
      float2 qa = *(const float2*)(qr + 2*tig);
      float2 qb = *(const float2*)(qr + 2*tig + 8);
      aq[mf][rs]   = cvt_h2(qa.x*SCL, qa.y*SCL);
      aq[mf][rs+2] = cvt_h2(qb.x*SCL, qb.y*SCL);
    }
  }
  __syncthreads();

  float o[3][2][4];
  #pragma unroll
  for (int mf = 0; mf < 3; mf++)
    #pragma unroll
    for (int cn = 0; cn < 2; cn++)
      #pragma unroll
      for (int r = 0; r < 4; r++) o[mf][cn][r] = 0.f;
  float lsd[3][4];
  #pragma unroll
  for (int mf = 0; mf < 3; mf++)
    #pragma unroll
    for (int r = 0; r < 4; r++) lsd[mf][r] = 0.f;

  const u32 zc = 0u;
  const int start = wid*3;   // warp-skewed ring start (linearized)

  #define STEP(T)                                                            \
  {                                                                          \
    const int lbase = (T)*512 + grp*64 + tig*16;                             \
    uint4 kk = *(const uint4*)(sK + lbase);                                  \
    uint4 vk = *(const uint4*)(sV + lbase);                                  \
    _Pragma("unroll")                                                        \
    for (int mf = 0; mf < 3; mf++){                                          \
      u32 d00, d01, d10, d11;                                                \
      mma_f16h(d00, d01, aq[mf], kk.x, kk.y, zc);                            \
      mma_f16h(d10, d11, aq[mf], kk.z, kk.w, zc);                            \
      u32 pa[4];                                                             \
      pa[0] = ex2h2(d00);                                                    \
      pa[1] = ex2h2(d01);                                                    \
      pa[2] = ex2h2(d10);                                                    \
      pa[3] = ex2h2(d11);                                                    \
      mma_f16(o[mf][0], pa, vk.x, vk.y);                                     \
      mma_f16(o[mf][1], pa, vk.z, vk.w);                                     \
      mma_f16(lsd[mf], pa, ONES16, ONES16);                                  \
    }                                                                        \
  }

  #pragma unroll 4
  for (int t = start; t < 24; t++) STEP(t)
  #pragma unroll 4
  for (int t = 0; t < start; t++) STEP(t)
  #undef STEP

  // ---- epilogue: HFMA2 conv + bias + normalize + store ----
  #pragma unroll
  for (int mf = 0; mf < 3; mf++){
    float rinv0 = 1.0f / lsd[mf][0];     // row grp (all D cols = row sum)
    float rinv1 = 1.0f / lsd[mf][2];     // row grp+8
    #pragma unroll
    for (int rs = 0; rs < 2; rs++){
      int m = wid*48 + mf*16 + grp + rs*8;
      int hl = m >> 3, w = m & 7;
      float rinv = rs ? rinv1 : rinv0;
      float* orow = out + bbase + (size_t)(hl*WWD + wb0 + w)*CC + c0;
      #pragma unroll
      for (int cn = 0; cn < 2; cn++){
        int cp = cn*4 + tig;     // channel pair index
        __half2 acc = sB2[cp];
        #pragma unroll
        for (int t = 0; t < 9; t++){
          int dy = t/3, dx = t - dy*3;
          acc = __hfma2(sW2[t*8+cp], haloh[((hl+dy)*10 + (w+dx))*8 + cp], acc);
        }
        float2 cv = __half22float2(acc);
        float2 res;
        res.x = o[mf][cn][rs*2]   * rinv + cv.x;
        res.y = o[mf][cn][rs*2+1] * rinv + cv.y;
        *(float2*)(orow + cn*8 + 2*tig) = res;
      }
    }
  }
}

// ---------------------------------------------------------------------------
extern "C" void kernel_launch(void* const* d_in, const int* in_sizes, int n_in,
                              void* d_out, int out_size){
  const float* q    = (const float*)d_in[0];
  const float* k    = (const float*)d_in[1];
  const float* v    = (const float*)d_in[2];
  const float* p1w  = (const float*)d_in[3];
  const float* p1b  = (const float*)d_in[4];
  const float* bng  = (const float*)d_in[5];
  const float* bnb  = (const float*)d_in[6];
  const float* bnm  = (const float*)d_in[7];
  const float* bnv  = (const float*)d_in[8];
  const float* p2w  = (const float*)d_in[9];
  const float* p2b  = (const float*)d_in[10];
  const float* dynw = (const float*)d_in[11];
  const float* dynb = (const float*)d_in[12];
  float* out = (float*)d_out;

  cudaFuncSetAttribute(attn_kernel, cudaFuncAttributeMaxDynamicSharedMemorySize, SMEM_SZ);

  pool_kernel<<<dim3(9, BB), 256>>>(v);
  proj_kernel<<<dim3(BB, 10), 128>>>(p1w, p1b, bng, bnb, bnm, bnv, p2w, p2b, dynw, dynb);
  attn_kernel<<<dim3(NHH, NWIN, BB), 256, SMEM_SZ>>>(q, k, v, out);
}

// round 17
// speedup vs baseline: 2.0454x; 1.0553x over previous
#include <cuda_runtime.h>
#include <cuda_bf16.h>
#include <cuda_fp16.h>
#include <cstdint>

#define BB 16
#define HH 48
#define WWD 48
#define CC 128
#define NHH 8
#define SSW 8
#define LL (HH*WWD)
#define HD (CC/NHH)          // 16
#define NWIN (WWD/SSW)       // 6
#define SEQ (HH*SSW)         // 384

// scratch (no allocations allowed)
__device__ float g_pooled[BB*9*CC];
__device__ float g_w[BB*CC*9];
__device__ float g_bias[BB*CC];

typedef unsigned long long ull;
typedef unsigned int u32;

// pack {lo=f16(x), hi=f16(y)}
__device__ __forceinline__ u32 cvt_h2(float x, float y){
  u32 d; asm("cvt.rn.f16x2.f32 %0,%1,%2;" : "=r"(d) : "f"(y), "f"(x)); return d;
}
__device__ __forceinline__ u32 ex2h2(u32 x){
  u32 d; asm("ex2.approx.f16x2 %0,%1;" : "=r"(d) : "r"(x)); return d;
}
// fp32-accumulate f16 MMA
__device__ __forceinline__ void mma_f16(float (&d)[4], const u32 (&a)[4], u32 b0, u32 b1){
  asm volatile("mma.sync.aligned.m16n8k16.row.col.f32.f16.f16.f32 "
    "{%0,%1,%2,%3}, {%4,%5,%6,%7}, {%8,%9}, {%0,%1,%2,%3};"
    : "+f"(d[0]), "+f"(d[1]), "+f"(d[2]), "+f"(d[3])
    : "r"(a[0]), "r"(a[1]), "r"(a[2]), "r"(a[3]), "r"(b0), "r"(b1));
}
// fp16-accumulate f16 MMA, separate zero C (no accumulator zeroing in loop)
__device__ __forceinline__ void mma_f16h(u32& d0, u32& d1, const u32 (&a)[4],
                                         u32 b0, u32 b1, u32 zc){
  asm volatile("mma.sync.aligned.m16n8k16.row.col.f16.f16.f16.f16 "
    "{%0,%1}, {%2,%3,%4,%5}, {%6,%7}, {%8,%9};"
    : "=r"(d0), "=r"(d1)
    : "r"(a[0]), "r"(a[1]), "r"(a[2]), "r"(a[3]), "r"(b0), "r"(b1),
      "r"(zc), "r"(zc));
}

// ---------------------------------------------------------------------------
// Kernel 1: adaptive avg pool to 3x3 (uniform 16x16 block means)
// R9 best config: grid (9, 16, 2), 512 threads, 8 float4 loads each
// ---------------------------------------------------------------------------
__global__ void pool_kernel(const float* __restrict__ v){
  const int bin = blockIdx.x, b = blockIdx.y, ch = blockIdx.z;
  const int ky = bin / 3, kx = bin - ky*3;
  const int tid = threadIdx.x;
  const int c4 = tid & 15, part = tid >> 4;    // 16 ch-groups, 32 parts
  const int row = part >> 1, wh = part & 1;    // 16 rows x 2 col-halves
  const int cg = ch*16 + c4;
  const float4* vb = (const float4*)(v + (size_t)b*LL*CC);
  const int h = ky*16 + row;
  const float4* p = vb + (size_t)(h*WWD + kx*16 + wh*8)*(CC/4) + cg;
  float4 s = make_float4(0.f,0.f,0.f,0.f);
  #pragma unroll
  for (int ww = 0; ww < 8; ww++){
    float4 t = p[ww*(CC/4)];
    s.x += t.x; s.y += t.y; s.z += t.z; s.w += t.w;
  }
  __shared__ float4 red[512];
  red[tid] = s; __syncthreads();
  #pragma unroll
  for (int off = 256; off >= 16; off >>= 1){
    if (tid < off){
      float4 o = red[tid+off];
      s.x += o.x; s.y += o.y; s.z += o.z; s.w += o.w;
      red[tid] = s;
    }
    __syncthreads();
  }
  if (tid < 16){
    s.x *= (1.f/256.f); s.y *= (1.f/256.f); s.z *= (1.f/256.f); s.w *= (1.f/256.f);
    ((float4*)g_pooled)[(b*9 + bin)*32 + ch*16 + tid] = s;
  }
}

// ---------------------------------------------------------------------------
// Kernel 2: proj MLP, one (batch, position) per block; pos 9 = global mean
// ---------------------------------------------------------------------------
__global__ void proj_kernel(const float* __restrict__ p1w, const float* __restrict__ p1b,
                            const float* __restrict__ bng, const float* __restrict__ bnb,
                            const float* __restrict__ bnm, const float* __restrict__ bnv,
                            const float* __restrict__ p2w, const float* __restrict__ p2b,
                            const float* __restrict__ dynw, const float* __restrict__ dynb){
  const int b = blockIdx.x, pos = blockIdx.y;
  const int tid = threadIdx.x;
  __shared__ float prow[128];
  __shared__ float act[32];

  {
    float s;
    if (pos < 9) s = g_pooled[(b*9 + pos)*CC + tid];
    else {
      s = 0.f;
      #pragma unroll
      for (int qq = 0; qq < 9; qq++) s += g_pooled[(b*9 + qq)*CC + tid];
      s *= (1.f/9.f);
    }
    prow[tid] = s;
  }
  __syncthreads();

  if (tid < 32){
    const int o = tid;
    float s = p1b[o];
    const float4* w = (const float4*)(p1w + o*CC);
    #pragma unroll 8
    for (int i = 0; i < 32; i++){
      float4 ww = w[i];
      s += ww.x*prow[4*i] + ww.y*prow[4*i+1] + ww.z*prow[4*i+2] + ww.w*prow[4*i+3];
    }
    float inv = rsqrtf(bnv[o] + 1e-5f);
    s = (s - bnm[o]) * (inv * bng[o]) + bnb[o];
    s = 0.5f * s * (1.f + erff(s * 0.70710678118654752f));
    act[o] = s;
  }
  __syncthreads();

  {
    const int c = tid;
    float y[4];
    #pragma unroll
    for (int g = 0; g < 4; g++){
      int oc = g*CC + c;
      float s = p2b[oc];
      const float4* w = (const float4*)(p2w + oc*32);
      #pragma unroll
      for (int i = 0; i < 8; i++){
        float4 ww = w[i];
        s += ww.x*act[4*i] + ww.y*act[4*i+1] + ww.z*act[4*i+2] + ww.w*act[4*i+3];
      }
      y[g] = s;
    }
    float m = fmaxf(fmaxf(y[0],y[1]), fmaxf(y[2],y[3]));
    float e0 = expf(y[0]-m), e1 = expf(y[1]-m), e2 = expf(y[2]-m), e3 = expf(y[3]-m);
    float rs = 1.f / (e0+e1+e2+e3);
    if (pos < 9){
      float wv = e0*dynw[(0*CC+c)*9+pos] + e1*dynw[(1*CC+c)*9+pos]
               + e2*dynw[(2*CC+c)*9+pos] + e3*dynw[(3*CC+c)*9+pos];
      g_w[(b*CC + c)*9 + pos] = wv * rs;
    } else {
      float bv = e0*dynb[0*CC+c] + e1*dynb[1*CC+c] + e2*dynb[2*CC+c] + e3*dynb[3*CC+c];
      g_bias[b*CC + c] = bv * rs;
    }
  }
}

// ---------------------------------------------------------------------------
// Kernel 3: tensor-core attention — R13 mainloop/epilogue; V fill rebuilt to
// process key-PAIRS so every shared store is STS.32 (half2 = {k0,k1}),
// halving V-fill store instructions (bit-identical smem contents).
// grid (8 heads, 6 wblks, 16 batches), 256 threads, 3 CTAs/SM
// ---------------------------------------------------------------------------
#define KOFF    0
#define VOFF    12288
#define HOFF    24576       // halo fp16: 50*10*16*2 = 16000
#define W2_OFF  40576
#define B2_OFF  40864
#define SMEM_SZ 40896
#define ONES16  0x3C003C00u

__global__ void __launch_bounds__(256, 3)
attn_kernel(const float* __restrict__ q, const float* __restrict__ k,
            const float* __restrict__ v, float* __restrict__ out){
  extern __shared__ char smem[];
  char* sK  = smem + KOFF;
  char* sV  = smem + VOFF;
  __half2* haloh = (__half2*)(smem + HOFF);   // [50*10][8] half2
  __half2* sW2 = (__half2*)(smem + W2_OFF);   // [9][8]
  __half2* sB2 = (__half2*)(smem + B2_OFF);   // [8]

  const int head = blockIdx.x, wblk = blockIdx.y, b = blockIdx.z;
  const int c0 = head*HD;
  const int wb0 = wblk*SSW;
  const int tid = threadIdx.x;
  const int wid = tid >> 5, lane = tid & 31;
  const int grp = lane >> 2, tig = lane & 3;
  const size_t bbase = (size_t)b*LL*CC;

  // ---- fill K (fp16, frag-packed: lane 16B = kh0|kh1) ----
  for (int i = tid; i < SEQ*4; i += 256){
    int key = i >> 2, dq = (i & 3)*4;
    int hj = key >> 3, wj = key & 7;
    float4 kv = *(const float4*)(k + bbase + (size_t)(hj*WWD + wb0 + wj)*CC + c0 + dq);
    u32 h0 = cvt_h2(kv.x, kv.y);
    u32 h1 = cvt_h2(kv.z, kv.w);
    int j0 = dq >> 1;                         // pair index 0,2,4,6
    int s0 = (j0 < 4) ? 2*j0 : 2*j0 - 7;
    int s1 = (j0+1 < 4) ? 2*(j0+1) : 2*(j0+1) - 7;
    int p0 = s0*4, p1 = s1*4;
    int step = key >> 4, r = key & 15;
    char* base = sK + step*512 + (r & 7)*64 + ((r >= 8) ? 8 : 0);
    *(u32*)(base + (p0 >> 3)*16 + (p0 & 7)) = h0;
    *(u32*)(base + (p1 >> 3)*16 + (p1 & 7)) = h1;
  }
  // ---- fill V by key-pairs (all STS.32) + interior halo from same loads ----
  for (int i = tid; i < 192*4; i += 256){
    int kp = i >> 2, dq = (i & 3)*4;
    int k0 = kp*2;
    int hj = k0 >> 3, wj = k0 & 7;           // wj even; k1 = k0+1 same row
    const float* vp = v + bbase + (size_t)(hj*WWD + wb0 + wj)*CC + c0 + dq;
    float4 v0 = *(const float4*)(vp);
    float4 v1 = *(const float4*)(vp + CC);
    float a0[4] = {v0.x, v0.y, v0.z, v0.w};
    float a1[4] = {v1.x, v1.y, v1.z, v1.w};
    int blk = k0 >> 4, r = k0 & 15;
    int pr = r >> 1;
    int slot = (r < 8) ? 2*pr : 2*(pr-4)+1;
    int q0 = slot*4;                          // parity-0 byte offset
    char* base = sV + blk*512 + (q0 >> 3)*16 + (q0 & 7);
    #pragma unroll
    for (int d = 0; d < 4; d++){
      int ch = dq + d;
      *(u32*)(base + (ch & 7)*64 + ((ch >= 8) ? 8 : 0)) = cvt_h2(a0[d], a1[d]);
    }
    // interior halo positions (hj+1, wj+1) and (hj+1, wj+2)
    int hpos = (hj + 1)*10 + (wj + 1);
    int cq = dq >> 1;
    haloh[hpos*8 + cq]       = __floats2half2_rn(a0[0], a0[1]);
    haloh[hpos*8 + cq + 1]   = __floats2half2_rn(a0[2], a0[3]);
    haloh[(hpos+1)*8 + cq]     = __floats2half2_rn(a1[0], a1[1]);
    haloh[(hpos+1)*8 + cq + 1] = __floats2half2_rn(a1[2], a1[3]);
  }
  // ---- boundary halo (116 positions x 4 ch-quads), bounds-checked ----
  for (int i = tid; i < 464; i += 256){
    int dq = i & 3, idx = i >> 2;        // idx in [0,116)
    int hh, ww;
    if (idx < 10){ hh = 0;  ww = idx; }
    else if (idx < 20){ hh = 49; ww = idx - 10; }
    else { int j = idx - 20; hh = 1 + (j >> 1); ww = (j & 1)*9; }
    int gh = hh - 1, gw = wb0 + ww - 1;
    float4 val = make_float4(0.f,0.f,0.f,0.f);
    if (gh >= 0 && gh < HH && gw >= 0 && gw < WWD)
      val = *(const float4*)(v + bbase + (size_t)(gh*WWD + gw)*CC + c0 + dq*4);
    haloh[(hh*10 + ww)*8 + dq*2]     = __floats2half2_rn(val.x, val.y);
    haloh[(hh*10 + ww)*8 + dq*2 + 1] = __floats2half2_rn(val.z, val.w);
  }
  if (tid < 72){
    int t = tid >> 3, i = tid & 7;
    sW2[t*8+i] = __floats2half2_rn(g_w[(b*CC + c0 + 2*i)*9 + t],
                                   g_w[(b*CC + c0 + 2*i+1)*9 + t]);
  }
  if (tid < 8)
    sB2[tid] = __floats2half2_rn(g_bias[b*CC + c0 + 2*tid],
                                 g_bias[b*CC + c0 + 2*tid+1]);

  // ---- Q fragments (scaled fp16) ----
  const float SCL = 0.36067376022224085f;  // 0.25 * log2(e)
  u32 aq[3][4];
  #pragma unroll
  for (int mf = 0; mf < 3; mf++){
    #pragma unroll
    for (int rs = 0; rs < 2; rs++){
      int m = wid*48 + mf*16 + grp + rs*8;     // query 0..383
      int hl = m >> 3, w = m & 7;
      const float* qr = q + bbase + (size_t)(hl*WWD + wb0 + w)*CC + c0;
      float2 qa = *(const float2*)(qr + 2*tig);
      float2 qb = *(const float2*)(qr + 2*tig + 8);
      aq[mf][rs]   = cvt_h2(qa.x*SCL, qa.y*SCL);
      aq[mf][rs+2] = cvt_h2(qb.x*SCL, qb.y*SCL);
    }
  }
  __syncthreads();

  float o[3][2][4];
  #pragma unroll
  for (int mf = 0; mf < 3; mf++)
    #pragma unroll
    for (int cn = 0; cn < 2; cn++)
      #pragma unroll
      for (int r = 0; r < 4; r++) o[mf][cn][r] = 0.f;
  float lsd[3][4];
  #pragma unroll
  for (int mf = 0; mf < 3; mf++)
    #pragma unroll
    for (int r = 0; r < 4; r++) lsd[mf][r] = 0.f;

  const u32 zc = 0u;
  const int start = wid*3;   // warp-skewed ring start (linearized)

  #define STEP(T)                                                            \
  {                                                                          \
    const int lbase = (T)*512 + grp*64 + tig*16;                             \
    uint4 kk = *(const uint4*)(sK + lbase);                                  \
    uint4 vk = *(const uint4*)(sV + lbase);                                  \
    _Pragma("unroll")                                                        \
    for (int mf = 0; mf < 3; mf++){                                          \
      u32 d00, d01, d10, d11;                                                \
      mma_f16h(d00, d01, aq[mf], kk.x, kk.y, zc);                            \
      mma_f16h(d10, d11, aq[mf], kk.z, kk.w, zc);                            \
      u32 pa[4];                                                             \
      pa[0] = ex2h2(d00);                                                    \
      pa[1] = ex2h2(d01);                                                    \
      pa[2] = ex2h2(d10);                                                    \
      pa[3] = ex2h2(d11);                                                    \
      mma_f16(o[mf][0], pa, vk.x, vk.y);                                     \
      mma_f16(o[mf][1], pa, vk.z, vk.w);                                     \
      mma_f16(lsd[mf], pa, ONES16, ONES16);                                  \
    }                                                                        \
  }

  #pragma unroll 4
  for (int t = start; t < 24; t++) STEP(t)
  #pragma unroll 4
  for (int t = 0; t < start; t++) STEP(t)
  #undef STEP

  // ---- epilogue: HFMA2 conv + bias + normalize + store ----
  #pragma unroll
  for (int mf = 0; mf < 3; mf++){
    float rinv0 = 1.0f / lsd[mf][0];     // row grp (all D cols = row sum)
    float rinv1 = 1.0f / lsd[mf][2];     // row grp+8
    #pragma unroll
    for (int rs = 0; rs < 2; rs++){
      int m = wid*48 + mf*16 + grp + rs*8;
      int hl = m >> 3, w = m & 7;
      float rinv = rs ? rinv1 : rinv0;
      float* orow = out + bbase + (size_t)(hl*WWD + wb0 + w)*CC + c0;
      #pragma unroll
      for (int cn = 0; cn < 2; cn++){
        int cp = cn*4 + tig;     // channel pair index
        __half2 acc = sB2[cp];
        #pragma unroll
        for (int t = 0; t < 9; t++){
          int dy = t/3, dx = t - dy*3;
          acc = __hfma2(sW2[t*8+cp], haloh[((hl+dy)*10 + (w+dx))*8 + cp], acc);
        }
        float2 cv = __half22float2(acc);
        float2 res;
        res.x = o[mf][cn][rs*2]   * rinv + cv.x;
        res.y = o[mf][cn][rs*2+1] * rinv + cv.y;
        *(float2*)(orow + cn*8 + 2*tig) = res;
      }
    }
  }
}

// ---------------------------------------------------------------------------
extern "C" void kernel_launch(void* const* d_in, const int* in_sizes, int n_in,
                              void* d_out, int out_size){
  const float* q    = (const float*)d_in[0];
  const float* k    = (const float*)d_in[1];
  const float* v    = (const float*)d_in[2];
  const float* p1w  = (const float*)d_in[3];
  const float* p1b  = (const float*)d_in[4];
  const float* bng  = (const float*)d_in[5];
  const float* bnb  = (const float*)d_in[6];
  const float* bnm  = (const float*)d_in[7];
  const float* bnv  = (const float*)d_in[8];
  const float* p2w  = (const float*)d_in[9];
  const float* p2b  = (const float*)d_in[10];
  const float* dynw = (const float*)d_in[11];
  const float* dynb = (const float*)d_in[12];
  float* out = (float*)d_out;

  cudaFuncSetAttribute(attn_kernel, cudaFuncAttributeMaxDynamicSharedMemorySize, SMEM_SZ);

  pool_kernel<<<dim3(9, BB, 2), 512>>>(v);
  proj_kernel<<<dim3(BB, 10), 128>>>(p1w, p1b, bng, bnb, bnm, bnv, p2w, p2b, dynw, dynb);
  attn_kernel<<<dim3(NHH, NWIN, BB), 256, SMEM_SZ>>>(q, k, v, out);
}